// round 12
// baseline (speedup 1.0000x reference)
#include <cuda_runtime.h>
#include <cuda_fp16.h>
#include <cstdint>

// ---------------------------------------------------------------------------
// 2D DCT-II, two-level parity folding, fp16 mma.sync (m16n8k16, fp32 accum).
// R7 geometry (128x128 CTA tile, 64x32 warp tiles, 2 CTA/SM), BK=64 chunks,
// 3-stage ring buffer -> ONE __syncthreads per chunk.
// Branches per pass (q = transform output index):
//   q odd   : K=256, u1  = x[n]-x[511-n],      tbl cos(pi(2n+1)(2r+1)/1024)
//   q = 4s  : K=128, u00 = lvl2(+) of lvl1(+), tbl cos(pi(2n+1)s/256)
//   q = 4s+2: K=128, u01 = lvl2(-) of lvl1(+), tbl cos(pi(2n+1)(2s+1)/512)
// Pass A CTAs cover i-quads {j0, 511-j0, 255-j0, 256+j0}; epilogue emits
// U1/U00/U01 (both fold levels in fp32) directly. Pass B is pure cp.async.
// ---------------------------------------------------------------------------

#define DCT_N 512
#define BATCH 128
#define KH    256
#define BM    128
#define BN    128
#define BK    64
#define APH   72             // A smem pitch (halfs): 64 + 8 pad
#define BPH   136            // B smem pitch (halfs): 128 + 8 pad
#define SPF   132            // epilogue staging pitch (floats)

#define A_BYTES (BM * APH * 2)        // 18432
#define B_BYTES (BK * BPH * 2)        // 17408
#define ST_BYTES (A_BYTES + B_BYTES)  // 35840
#define SMEM_BYTES (3 * ST_BYTES)     // 107520 (> staging 128*132*4 = 67584)

__device__ __align__(16) __half g_T1 [KH * KH];     // [n][r] cos(pi(2n+1)(2r+1)/1024)
__device__ __align__(16) __half g_TEE[128 * 128];   // [n][s] cos(pi(2n+1)s/256)
__device__ __align__(16) __half g_TEO[128 * 128];   // [n][s] cos(pi(2n+1)(2s+1)/512)
__device__ __align__(16) __half g_U1 [(size_t)BATCH * DCT_N * 256];
__device__ __align__(16) __half g_U00[(size_t)BATCH * DCT_N * 128];
__device__ __align__(16) __half g_U01[(size_t)BATCH * DCT_N * 128];

__global__ void init_tables_kernel() {
    int idx = blockIdx.x * blockDim.x + threadIdx.x;
    if (idx < KH * KH) {
        int n = idx >> 8, r = idx & 255;
        g_T1[idx] = __float2half_rn(
            cospif((2.0f * n + 1.0f) * (2.0f * r + 1.0f) * (1.0f / 1024.0f)));
    } else if (idx < KH * KH + 128 * 128) {
        int j = idx - KH * KH;
        int n = j >> 7, s = j & 127;
        g_TEE[j] = __float2half_rn(
            cospif((2.0f * n + 1.0f) * (float)s * (1.0f / 256.0f)));
    } else if (idx < KH * KH + 2 * 128 * 128) {
        int j = idx - KH * KH - 128 * 128;
        int n = j >> 7, s = j & 127;
        g_TEO[j] = __float2half_rn(
            cospif((2.0f * n + 1.0f) * (2.0f * s + 1.0f) * (1.0f / 512.0f)));
    }
}

__device__ __forceinline__ uint32_t smem_u32(const void* p) {
    uint32_t a;
    asm("{ .reg .u64 t; cvta.to.shared.u64 t, %1; cvt.u32.u64 %0, t; }" : "=r"(a) : "l"(p));
    return a;
}
__device__ __forceinline__ void cp16(uint32_t dst, const void* src) {
    asm volatile("cp.async.cg.shared.global [%0], [%1], 16;" :: "r"(dst), "l"(src));
}
#define CP_COMMIT() asm volatile("cp.async.commit_group;" ::: "memory")
#define CP_WAIT(n)  asm volatile("cp.async.wait_group %0;" :: "n"(n) : "memory")

__device__ __forceinline__ void ldsm4(uint32_t r[4], uint32_t addr) {
    asm volatile("ldmatrix.sync.aligned.m8n8.x4.shared.b16 {%0,%1,%2,%3}, [%4];"
                 : "=r"(r[0]), "=r"(r[1]), "=r"(r[2]), "=r"(r[3]) : "r"(addr));
}
__device__ __forceinline__ void ldsm4t(uint32_t r[4], uint32_t addr) {
    asm volatile("ldmatrix.sync.aligned.m8n8.x4.trans.shared.b16 {%0,%1,%2,%3}, [%4];"
                 : "=r"(r[0]), "=r"(r[1]), "=r"(r[2]), "=r"(r[3]) : "r"(addr));
}
__device__ __forceinline__ void mma_f16(float c[4], const uint32_t a[4],
                                        uint32_t b0, uint32_t b1) {
    asm volatile(
        "mma.sync.aligned.m16n8k16.row.col.f32.f16.f16.f32 "
        "{%0,%1,%2,%3},{%4,%5,%6,%7},{%8,%9},{%0,%1,%2,%3};"
        : "+f"(c[0]), "+f"(c[1]), "+f"(c[2]), "+f"(c[3])
        : "r"(a[0]), "r"(a[1]), "r"(a[2]), "r"(a[3]), "r"(b0), "r"(b1));
}
__device__ __forceinline__ uint32_t packh2(float lo, float hi) {
    __half2 h = __floats2half2_rn(lo, hi);
    return *(uint32_t*)&h;
}

// MODE 0: A-source = img (fp32, folded inline), out = U1/U00/U01 (fp16)
// MODE 1: A-source = U1/U00/U01 (pure cp.async), out = d_out (fp32, scaled)
template <int MODE>
__global__ __launch_bounds__(256, 2)
void dct_fold_fp16(const float* __restrict__ img, float* __restrict__ out)
{
    extern __shared__ __align__(16) char smem[];
    const uint32_t sb = smem_u32(smem);
    float* Sf = (float*)smem;

    const int tid = threadIdx.x, lane = tid & 31, warp = tid >> 5;
    const int jx  = blockIdx.x;          // 0,1: odd-q blocks; 2: q=4s; 3: q=4s+2
    const int bat = blockIdx.z;
    const int yb  = blockIdx.y;
    const bool ODD = (jx < 2);
    const int  NC  = ODD ? 4 : 2;        // K / BK
    const int  rC  = ODD ? jx * BN : 0;
    const int  TW  = ODD ? KH : 128;     // table row width
    const __half* tbl = ODD ? g_T1 : (jx == 2 ? g_TEE : g_TEO);
    const float sg2 = (jx == 3) ? -1.0f : 1.0f;
    const int wm = (warp & 1) * 64, wn = (warp >> 1) * 32;
    const int grp = lane >> 2, tig = lane & 3;

    const float* Ef = img + (size_t)bat * DCT_N * DCT_N;
    const __half* Ub =
        ODD ? g_U1 + (size_t)bat * DCT_N * 256
            : (jx == 2 ? g_U00 : g_U01) + (size_t)bat * DCT_N * 128;
    const int UW = ODD ? 256 : 128;
    float* Of = out + (size_t)bat * DCT_N * DCT_N;

    const int aLaneOff =
        ((wm + (lane & 7) + ((lane >> 3) & 1) * 8) * APH + (lane >> 4) * 8) * 2;
    const int bLaneOff =
        (((((lane >> 4) & 1) * 8) + (lane & 7)) * BPH + ((lane >> 3) & 1) * 8) * 2;

    float acc[4][4][4];
#pragma unroll
    for (int mi = 0; mi < 4; ++mi)
#pragma unroll
        for (int ni = 0; ni < 4; ++ni)
#pragma unroll
            for (int r = 0; r < 4; ++r) acc[mi][ni][r] = 0.0f;

    // A-loader coords: 128 rows x 8 granules(8h) -> 4 per thread
    int rowA[4], khh[4];
    const float* rowPtr[4];
#pragma unroll
    for (int i = 0; i < 4; ++i) {
        int g = tid + i * 256;
        rowA[i] = g >> 3;
        khh[i] = (g & 7) * 8;
        if (MODE == 0) {
            int l = rowA[i];
            int j0 = 32 * yb + (l & 31);
            int quad = l >> 5;
            int gi = (quad == 0) ? j0
                   : (quad == 1) ? 511 - j0
                   : (quad == 2) ? 255 - j0
                                 : 256 + j0;
            rowPtr[i] = Ef + (size_t)gi * DCT_N;
        }
    }
    // B-loader coords: 64 rows x 16 granules -> 4 per thread
    int rowB[4], nB[4];
#pragma unroll
    for (int i = 0; i < 4; ++i) {
        int g = tid + i * 256;
        rowB[i] = g >> 4;
        nB[i] = (g & 15) * 8;
    }

    uint4 oReg[4];
    auto ldA = [&](int t) {   // MODE 0 only: fold img -> fp16 regs
#pragma unroll
        for (int i = 0; i < 4; ++i) {
            int kp = t * BK + khh[i];
            const float* base = rowPtr[i];
            float4 F0 = *(const float4*)(base + kp);
            float4 F1 = *(const float4*)(base + kp + 4);
            float4 R1 = *(const float4*)(base + 508 - kp);
            float4 R0 = *(const float4*)(base + 504 - kp);
            if (ODD) {
                oReg[i].x = packh2(F0.x - R1.w, F0.y - R1.z);
                oReg[i].y = packh2(F0.z - R1.y, F0.w - R1.x);
                oReg[i].z = packh2(F1.x - R0.w, F1.y - R0.z);
                oReg[i].w = packh2(F1.z - R0.y, F1.w - R0.x);
            } else {
                float4 C1 = *(const float4*)(base + 252 - kp);
                float4 C0 = *(const float4*)(base + 248 - kp);
                float4 D0 = *(const float4*)(base + 256 + kp);
                float4 D1 = *(const float4*)(base + 260 + kp);
                oReg[i].x = packh2(fmaf(sg2, C1.w + D0.x, F0.x + R1.w),
                                   fmaf(sg2, C1.z + D0.y, F0.y + R1.z));
                oReg[i].y = packh2(fmaf(sg2, C1.y + D0.z, F0.z + R1.y),
                                   fmaf(sg2, C1.x + D0.w, F0.w + R1.x));
                oReg[i].z = packh2(fmaf(sg2, C0.w + D1.x, F1.x + R0.w),
                                   fmaf(sg2, C0.z + D1.y, F1.y + R0.z));
                oReg[i].w = packh2(fmaf(sg2, C0.y + D1.z, F1.z + R0.y),
                                   fmaf(sg2, C0.x + D1.w, F1.w + R0.x));
            }
        }
    };
    auto stsA = [&](uint32_t off) {
#pragma unroll
        for (int i = 0; i < 4; ++i)
            *(uint4*)(smem + off + (rowA[i] * APH + khh[i]) * 2) = oReg[i];
    };
    auto cpA = [&](int t, uint32_t off) {   // MODE 1: pure async
#pragma unroll
        for (int i = 0; i < 4; ++i) {
            uint32_t dst = sb + off + (rowA[i] * APH + khh[i]) * 2;
            const __half* src = Ub + (size_t)(yb * BM + rowA[i]) * UW + t * BK + khh[i];
            cp16(dst, src);
        }
    };
    auto cpB = [&](int t, uint32_t off) {
#pragma unroll
        for (int i = 0; i < 4; ++i) {
            uint32_t dst = sb + off + (rowB[i] * BPH + nB[i]) * 2;
            const __half* src = tbl + (size_t)(t * BK + rowB[i]) * TW + rC + nB[i];
            cp16(dst, src);
        }
    };
    auto compute = [&](uint32_t aOff, uint32_t bOff) {
#pragma unroll
        for (int ks = 0; ks < 4; ++ks) {
            uint32_t a[4][4];
#pragma unroll
            for (int mi = 0; mi < 4; ++mi)
                ldsm4(a[mi], sb + aOff + aLaneOff + mi * (16 * APH * 2) + ks * 32);
            uint32_t bq[2][4];
#pragma unroll
            for (int pr = 0; pr < 2; ++pr)
                ldsm4t(bq[pr], sb + bOff + bLaneOff + ks * (16 * BPH * 2)
                               + (wn + pr * 16) * 2);
#pragma unroll
            for (int mi = 0; mi < 4; ++mi)
#pragma unroll
                for (int ni = 0; ni < 4; ++ni)
                    mma_f16(acc[mi][ni], a[mi],
                            bq[ni >> 1][ni & 1], bq[ni >> 1][2 + (ni & 1)]);
        }
    };

    // 3-stage ring
    uint32_t aOff[3], bOff[3];
#pragma unroll
    for (int s = 0; s < 3; ++s) {
        aOff[s] = s * ST_BYTES;
        bOff[s] = aOff[s] + A_BYTES;
    }

    // ---- prologue: fill stages 0,1; regs for chunk 2 ----
    if (MODE == 0) {
        ldA(0); stsA(aOff[0]); cpB(0, bOff[0]); CP_COMMIT();
        ldA(1); stsA(aOff[1]); cpB(1, bOff[1]); CP_COMMIT();
        if (2 < NC) ldA(2);
    } else {
        cpA(0, aOff[0]); cpB(0, bOff[0]); CP_COMMIT();
        cpA(1, aOff[1]); cpB(1, bOff[1]); CP_COMMIT();
    }

    // ---- mainloop: ONE barrier per BK=64 chunk ----
#pragma unroll 1
    for (int t = 0; t < NC; ++t) {
        if (t < NC - 1) { CP_WAIT(1); } else { CP_WAIT(0); }
        __syncthreads();   // chunk t resident; all warps past compute(t-1)
        if (t + 2 < NC) {
            int s = (t + 2) % 3;      // == (t-1)%3: freed by the barrier above
            if (MODE == 0) stsA(aOff[s]);
            else           cpA(t + 2, aOff[s]);
            cpB(t + 2, bOff[s]);
            CP_COMMIT();
            if (MODE == 0 && t + 3 < NC) ldA(t + 3);
        }
        compute(aOff[t % 3], bOff[t % 3]);
    }
    __syncthreads();

    // ---- epilogue: stage full 128x128 fp32 tile (Sf[rl][ii]) ----
#pragma unroll
    for (int mi = 0; mi < 4; ++mi)
#pragma unroll
        for (int ni = 0; ni < 4; ++ni)
#pragma unroll
            for (int h = 0; h < 2; ++h)
#pragma unroll
                for (int c = 0; c < 2; ++c) {
                    int rl = wn + ni * 8 + 2 * tig + c;
                    int ii = wm + mi * 16 + grp + 8 * h;
                    Sf[rl * SPF + ii] = acc[mi][ni][2 * h + c];
                }
    __syncthreads();

    const float is2 = 0.70710678118654752440f;
    if (MODE == 0) {
        __half* U1w  = g_U1  + (size_t)bat * DCT_N * 256;
        __half* U00w = g_U00 + (size_t)bat * DCT_N * 128;
        __half* U01w = g_U01 + (size_t)bat * DCT_N * 128;
#pragma unroll
        for (int it = 0; it < 4; ++it) {
            int idx = it * 256 + tid;
            int rl = idx >> 3;
            int jj4 = (idx & 7) * 4;
            int q = ODD ? (2 * (rC + rl) + 1) : (jx == 2 ? 4 * rl : 4 * rl + 2);
            int j0 = 32 * yb + jj4;
            const float* Sr = Sf + rl * SPF;
            float4 a = *(const float4*)(Sr + jj4);        // T[j0..]
            float4 b = *(const float4*)(Sr + 32 + jj4);   // T[511-j0..]
            float4 c = *(const float4*)(Sr + 64 + jj4);   // T[255-j0..]
            float4 d = *(const float4*)(Sr + 96 + jj4);   // T[256+j0..]
            uint2 u1f, u1r, u00, u01;
            u1f.x = packh2(a.x - b.x, a.y - b.y);
            u1f.y = packh2(a.z - b.z, a.w - b.w);
            u1r.x = packh2(c.w - d.w, c.z - d.z);
            u1r.y = packh2(c.y - d.y, c.x - d.x);
            float e0 = a.x + b.x, e1 = a.y + b.y, e2 = a.z + b.z, e3 = a.w + b.w;
            float f0 = c.x + d.x, f1 = c.y + d.y, f2 = c.z + d.z, f3 = c.w + d.w;
            u00.x = packh2(e0 + f0, e1 + f1);
            u00.y = packh2(e2 + f2, e3 + f3);
            u01.x = packh2(e0 - f0, e1 - f1);
            u01.y = packh2(e2 - f2, e3 - f3);
            *(uint2*)(U1w + (size_t)q * 256 + j0)        = u1f;
            *(uint2*)(U1w + (size_t)q * 256 + 252 - j0)  = u1r;
            *(uint2*)(U00w + (size_t)q * 128 + j0)       = u00;
            *(uint2*)(U01w + (size_t)q * 128 + j0)       = u01;
        }
    } else {
#pragma unroll
        for (int it = 0; it < 16; ++it) {
            int idx = it * 256 + tid;
            int rl = idx >> 5, i4 = (idx & 31) * 4;
            int prow = ODD ? (2 * (rC + rl) + 1) : (jx == 2 ? 4 * rl : 4 * rl + 2);
            float4 v = *(float4*)(Sf + rl * SPF + i4);
            float sc = (2.0f / 512.0f) * (prow == 0 ? is2 : 1.0f);
            v.x *= sc; v.y *= sc; v.z *= sc; v.w *= sc;
            if (yb * BM + i4 == 0) v.x *= is2;
            __stcs((float4*)(Of + (size_t)prow * DCT_N + yb * BM + i4), v);
        }
    }
}

extern "C" void kernel_launch(void* const* d_in, const int* in_sizes, int n_in,
                              void* d_out, int out_size)
{
    const float* img = (const float*)d_in[0];
    float* out = (float*)d_out;

    static bool attr_set = false;
    if (!attr_set) {
        cudaFuncSetAttribute(dct_fold_fp16<0>,
                             cudaFuncAttributeMaxDynamicSharedMemorySize, SMEM_BYTES);
        cudaFuncSetAttribute(dct_fold_fp16<1>,
                             cudaFuncAttributeMaxDynamicSharedMemorySize, SMEM_BYTES);
        attr_set = true;
    }

    const int tbl_elems = KH * KH + 2 * 128 * 128;   // 98304
    init_tables_kernel<<<(tbl_elems + 255) / 256, 256>>>();

    dim3 grid(4, 4, BATCH);   // jx: {odd0, odd1, ee, eo}
    dct_fold_fp16<0><<<grid, 256, SMEM_BYTES>>>(img, out);
    dct_fold_fp16<1><<<grid, 256, SMEM_BYTES>>>(img, out);
}

// round 13
// speedup vs baseline: 1.0923x; 1.0923x over previous
#include <cuda_runtime.h>
#include <cuda_fp16.h>
#include <cstdint>

// ---------------------------------------------------------------------------
// 2D DCT-II, two-level parity folding, fp16 mma.sync (m16n8k16, fp32 accum).
// R7 schedule (verified 170.5us): 128x128 CTA tile, 64x32 warp tiles,
// 2 CTA/SM, BK=64, 2-stage buffers, one barrier per chunk.
// This round: pass-B epilogue stores directly from accumulators (sector-
// efficient STG.32), removing the smem staging roundtrip and 2 barriers.
// Branches per pass (q = transform output index):
//   q odd   : K=256, u1  = x[n]-x[511-n],      tbl cos(pi(2n+1)(2r+1)/1024)
//   q = 4s  : K=128, u00 = lvl2(+) of lvl1(+), tbl cos(pi(2n+1)s/256)
//   q = 4s+2: K=128, u01 = lvl2(-) of lvl1(+), tbl cos(pi(2n+1)(2s+1)/512)
// Pass A CTAs cover i-quads {j0, 511-j0, 255-j0, 256+j0}; epilogue emits
// U1/U00/U01 (both fold levels in fp32) directly. Pass B is pure cp.async.
// ---------------------------------------------------------------------------

#define DCT_N 512
#define BATCH 128
#define KH    256
#define BM    128
#define BN    128
#define BK    64
#define APH   72             // A smem pitch (halfs)
#define BPH   136            // B smem pitch (halfs)
#define SPF   132            // epilogue staging pitch (floats)

#define OFF_A0 0
#define OFF_A1 18432
#define OFF_B0 36864
#define OFF_B1 54272
#define SMEM_BYTES 71680

__device__ __align__(16) __half g_T1 [KH * KH];     // [n][r] cos(pi(2n+1)(2r+1)/1024)
__device__ __align__(16) __half g_TEE[128 * 128];   // [n][s] cos(pi(2n+1)s/256)
__device__ __align__(16) __half g_TEO[128 * 128];   // [n][s] cos(pi(2n+1)(2s+1)/512)
__device__ __align__(16) __half g_U1 [(size_t)BATCH * DCT_N * 256];
__device__ __align__(16) __half g_U00[(size_t)BATCH * DCT_N * 128];
__device__ __align__(16) __half g_U01[(size_t)BATCH * DCT_N * 128];

__global__ void init_tables_kernel() {
    int idx = blockIdx.x * blockDim.x + threadIdx.x;
    if (idx < KH * KH) {
        int n = idx >> 8, r = idx & 255;
        g_T1[idx] = __float2half_rn(
            cospif((2.0f * n + 1.0f) * (2.0f * r + 1.0f) * (1.0f / 1024.0f)));
    } else if (idx < KH * KH + 128 * 128) {
        int j = idx - KH * KH;
        int n = j >> 7, s = j & 127;
        g_TEE[j] = __float2half_rn(
            cospif((2.0f * n + 1.0f) * (float)s * (1.0f / 256.0f)));
    } else if (idx < KH * KH + 2 * 128 * 128) {
        int j = idx - KH * KH - 128 * 128;
        int n = j >> 7, s = j & 127;
        g_TEO[j] = __float2half_rn(
            cospif((2.0f * n + 1.0f) * (2.0f * s + 1.0f) * (1.0f / 512.0f)));
    }
}

__device__ __forceinline__ uint32_t smem_u32(const void* p) {
    uint32_t a;
    asm("{ .reg .u64 t; cvta.to.shared.u64 t, %1; cvt.u32.u64 %0, t; }" : "=r"(a) : "l"(p));
    return a;
}
__device__ __forceinline__ void cp16(uint32_t dst, const void* src) {
    asm volatile("cp.async.cg.shared.global [%0], [%1], 16;" :: "r"(dst), "l"(src));
}
#define CP_COMMIT() asm volatile("cp.async.commit_group;" ::: "memory")
#define CP_WAIT0()  asm volatile("cp.async.wait_group 0;" ::: "memory")

__device__ __forceinline__ void ldsm4(uint32_t r[4], uint32_t addr) {
    asm volatile("ldmatrix.sync.aligned.m8n8.x4.shared.b16 {%0,%1,%2,%3}, [%4];"
                 : "=r"(r[0]), "=r"(r[1]), "=r"(r[2]), "=r"(r[3]) : "r"(addr));
}
__device__ __forceinline__ void ldsm4t(uint32_t r[4], uint32_t addr) {
    asm volatile("ldmatrix.sync.aligned.m8n8.x4.trans.shared.b16 {%0,%1,%2,%3}, [%4];"
                 : "=r"(r[0]), "=r"(r[1]), "=r"(r[2]), "=r"(r[3]) : "r"(addr));
}
__device__ __forceinline__ void mma_f16(float c[4], const uint32_t a[4],
                                        uint32_t b0, uint32_t b1) {
    asm volatile(
        "mma.sync.aligned.m16n8k16.row.col.f32.f16.f16.f32 "
        "{%0,%1,%2,%3},{%4,%5,%6,%7},{%8,%9},{%0,%1,%2,%3};"
        : "+f"(c[0]), "+f"(c[1]), "+f"(c[2]), "+f"(c[3])
        : "r"(a[0]), "r"(a[1]), "r"(a[2]), "r"(a[3]), "r"(b0), "r"(b1));
}
__device__ __forceinline__ uint32_t packh2(float lo, float hi) {
    __half2 h = __floats2half2_rn(lo, hi);
    return *(uint32_t*)&h;
}

// MODE 0: A-source = img (fp32, folded inline), out = U1/U00/U01 (fp16)
// MODE 1: A-source = U1/U00/U01 (pure cp.async), out = d_out (fp32, scaled)
template <int MODE>
__global__ __launch_bounds__(256, 2)
void dct_fold_fp16(const float* __restrict__ img, float* __restrict__ out)
{
    extern __shared__ __align__(16) char smem[];
    const uint32_t sb = smem_u32(smem);
    float* Sf = (float*)smem;

    const int tid = threadIdx.x, lane = tid & 31, warp = tid >> 5;
    const int jx  = blockIdx.x;          // 0,1: odd-q blocks; 2: q=4s; 3: q=4s+2
    const int bat = blockIdx.z;
    const int yb  = blockIdx.y;
    const bool ODD = (jx < 2);
    const int  NT  = ODD ? 4 : 2;        // K / BK
    const int  rC  = ODD ? jx * BN : 0;
    const int  TW  = ODD ? KH : 128;     // table row width
    const __half* tbl = ODD ? g_T1 : (jx == 2 ? g_TEE : g_TEO);
    const float sg2 = (jx == 3) ? -1.0f : 1.0f;
    const int wm = (warp & 1) * 64, wn = (warp >> 1) * 32;
    const int grp = lane >> 2, tig = lane & 3;

    const float* Ef = img + (size_t)bat * DCT_N * DCT_N;
    const __half* Ub =
        ODD ? g_U1 + (size_t)bat * DCT_N * 256
            : (jx == 2 ? g_U00 : g_U01) + (size_t)bat * DCT_N * 128;
    const int UW = ODD ? 256 : 128;
    float* Of = out + (size_t)bat * DCT_N * DCT_N;

    const int aLaneOff =
        ((wm + (lane & 7) + ((lane >> 3) & 1) * 8) * APH + (lane >> 4) * 8) * 2;
    const int bLaneOff =
        (((((lane >> 4) & 1) * 8) + (lane & 7)) * BPH + ((lane >> 3) & 1) * 8) * 2;

    float acc[4][4][4];
#pragma unroll
    for (int mi = 0; mi < 4; ++mi)
#pragma unroll
        for (int ni = 0; ni < 4; ++ni)
#pragma unroll
            for (int r = 0; r < 4; ++r) acc[mi][ni][r] = 0.0f;

    // A-loader coords: 128 rows x 8 granules(8h) -> 4 per thread
    int rowA[4], khh[4];
    const float* rowPtr[4];
#pragma unroll
    for (int i = 0; i < 4; ++i) {
        int g = tid + i * 256;
        rowA[i] = g >> 3;
        khh[i] = (g & 7) * 8;
        if (MODE == 0) {
            int l = rowA[i];
            int j0 = 32 * yb + (l & 31);
            int quad = l >> 5;
            int gi = (quad == 0) ? j0
                   : (quad == 1) ? 511 - j0
                   : (quad == 2) ? 255 - j0
                                 : 256 + j0;
            rowPtr[i] = Ef + (size_t)gi * DCT_N;
        }
    }
    // B-loader coords: 64 rows x 16 granules -> 4 per thread
    int rowB[4], nB[4];
#pragma unroll
    for (int i = 0; i < 4; ++i) {
        int g = tid + i * 256;
        rowB[i] = g >> 4;
        nB[i] = (g & 15) * 8;
    }

    uint4 oReg[4];
    auto ldA = [&](int t) {   // MODE 0 only: fold img -> fp16 regs
#pragma unroll
        for (int i = 0; i < 4; ++i) {
            int kp = t * BK + khh[i];
            const float* base = rowPtr[i];
            float4 F0 = *(const float4*)(base + kp);
            float4 F1 = *(const float4*)(base + kp + 4);
            float4 R1 = *(const float4*)(base + 508 - kp);
            float4 R0 = *(const float4*)(base + 504 - kp);
            if (ODD) {
                oReg[i].x = packh2(F0.x - R1.w, F0.y - R1.z);
                oReg[i].y = packh2(F0.z - R1.y, F0.w - R1.x);
                oReg[i].z = packh2(F1.x - R0.w, F1.y - R0.z);
                oReg[i].w = packh2(F1.z - R0.y, F1.w - R0.x);
            } else {
                float4 C1 = *(const float4*)(base + 252 - kp);
                float4 C0 = *(const float4*)(base + 248 - kp);
                float4 D0 = *(const float4*)(base + 256 + kp);
                float4 D1 = *(const float4*)(base + 260 + kp);
                oReg[i].x = packh2(fmaf(sg2, C1.w + D0.x, F0.x + R1.w),
                                   fmaf(sg2, C1.z + D0.y, F0.y + R1.z));
                oReg[i].y = packh2(fmaf(sg2, C1.y + D0.z, F0.z + R1.y),
                                   fmaf(sg2, C1.x + D0.w, F0.w + R1.x));
                oReg[i].z = packh2(fmaf(sg2, C0.w + D1.x, F1.x + R0.w),
                                   fmaf(sg2, C0.z + D1.y, F1.y + R0.z));
                oReg[i].w = packh2(fmaf(sg2, C0.y + D1.z, F1.z + R0.y),
                                   fmaf(sg2, C0.x + D1.w, F1.w + R0.x));
            }
        }
    };
    auto stsA = [&](int off) {
#pragma unroll
        for (int i = 0; i < 4; ++i)
            *(uint4*)(smem + off + (rowA[i] * APH + khh[i]) * 2) = oReg[i];
    };
    auto cpA = [&](int t, int off) {   // MODE 1: pure async
#pragma unroll
        for (int i = 0; i < 4; ++i) {
            uint32_t dst = sb + off + (rowA[i] * APH + khh[i]) * 2;
            const __half* src = Ub + (size_t)(yb * BM + rowA[i]) * UW + t * BK + khh[i];
            cp16(dst, src);
        }
    };
    auto cpB = [&](int t, int off) {
#pragma unroll
        for (int i = 0; i < 4; ++i) {
            uint32_t dst = sb + off + (rowB[i] * BPH + nB[i]) * 2;
            const __half* src = tbl + (size_t)(t * BK + rowB[i]) * TW + rC + nB[i];
            cp16(dst, src);
        }
    };
    auto compute = [&](int aOff, int bOff) {
#pragma unroll
        for (int ks = 0; ks < 4; ++ks) {
            uint32_t a[4][4];
#pragma unroll
            for (int mi = 0; mi < 4; ++mi)
                ldsm4(a[mi], sb + aOff + aLaneOff + mi * (16 * APH * 2) + ks * 32);
            uint32_t bq[2][4];
#pragma unroll
            for (int pr = 0; pr < 2; ++pr)
                ldsm4t(bq[pr], sb + bOff + bLaneOff + ks * (16 * BPH * 2)
                               + (wn + pr * 16) * 2);
#pragma unroll
            for (int mi = 0; mi < 4; ++mi)
#pragma unroll
                for (int ni = 0; ni < 4; ++ni)
                    mma_f16(acc[mi][ni], a[mi],
                            bq[ni >> 1][ni & 1], bq[ni >> 1][2 + (ni & 1)]);
        }
    };

    const int aOffs[2] = { OFF_A0, OFF_A1 };
    const int bOffs[2] = { OFF_B0, OFF_B1 };

    // ---- prologue ----
    if (MODE == 0) { ldA(0); stsA(aOffs[0]); }
    else           { cpA(0, aOffs[0]); }
    cpB(0, bOffs[0]);
    CP_COMMIT();
    if (MODE == 0) ldA(1);
    CP_WAIT0();
    __syncthreads();

    // ---- mainloop (R7 schedule, untouched) ----
#pragma unroll 1
    for (int t = 0; t < NT; ++t) {
        if (t + 1 < NT) {
            if (MODE == 0) stsA(aOffs[(t + 1) & 1]);
            else           cpA(t + 1, aOffs[(t + 1) & 1]);
            cpB(t + 1, bOffs[(t + 1) & 1]);
            CP_COMMIT();
            if (MODE == 0 && t + 2 < NT) ldA(t + 2);
        }
        compute(aOffs[t & 1], bOffs[t & 1]);
        if (t + 1 < NT) {
            CP_WAIT0();
            __syncthreads();
        }
    }

    const float is2 = 0.70710678118654752440f;
    if (MODE == 0) {
        // ---- staged epilogue (cross-warp folds need smem) ----
        __syncthreads();
#pragma unroll
        for (int mi = 0; mi < 4; ++mi)
#pragma unroll
            for (int ni = 0; ni < 4; ++ni)
#pragma unroll
                for (int h = 0; h < 2; ++h)
#pragma unroll
                    for (int c = 0; c < 2; ++c) {
                        int rl = wn + ni * 8 + 2 * tig + c;
                        int ii = wm + mi * 16 + grp + 8 * h;
                        Sf[rl * SPF + ii] = acc[mi][ni][2 * h + c];
                    }
        __syncthreads();

        __half* U1w  = g_U1  + (size_t)bat * DCT_N * 256;
        __half* U00w = g_U00 + (size_t)bat * DCT_N * 128;
        __half* U01w = g_U01 + (size_t)bat * DCT_N * 128;
#pragma unroll
        for (int it = 0; it < 4; ++it) {
            int idx = it * 256 + tid;
            int rl = idx >> 3;
            int jj4 = (idx & 7) * 4;
            int q = ODD ? (2 * (rC + rl) + 1) : (jx == 2 ? 4 * rl : 4 * rl + 2);
            int j0 = 32 * yb + jj4;
            const float* Sr = Sf + rl * SPF;
            float4 a = *(const float4*)(Sr + jj4);        // T[j0..]
            float4 b = *(const float4*)(Sr + 32 + jj4);   // T[511-j0..]
            float4 c = *(const float4*)(Sr + 64 + jj4);   // T[255-j0..]
            float4 d = *(const float4*)(Sr + 96 + jj4);   // T[256+j0..]
            uint2 u1f, u1r, u00, u01;
            u1f.x = packh2(a.x - b.x, a.y - b.y);
            u1f.y = packh2(a.z - b.z, a.w - b.w);
            u1r.x = packh2(c.w - d.w, c.z - d.z);
            u1r.y = packh2(c.y - d.y, c.x - d.x);
            float e0 = a.x + b.x, e1 = a.y + b.y, e2 = a.z + b.z, e3 = a.w + b.w;
            float f0 = c.x + d.x, f1 = c.y + d.y, f2 = c.z + d.z, f3 = c.w + d.w;
            u00.x = packh2(e0 + f0, e1 + f1);
            u00.y = packh2(e2 + f2, e3 + f3);
            u01.x = packh2(e0 - f0, e1 - f1);
            u01.y = packh2(e2 - f2, e3 - f3);
            *(uint2*)(U1w + (size_t)q * 256 + j0)        = u1f;
            *(uint2*)(U1w + (size_t)q * 256 + 252 - j0)  = u1r;
            *(uint2*)(U00w + (size_t)q * 128 + j0)       = u00;
            *(uint2*)(U01w + (size_t)q * 128 + j0)       = u01;
        }
    } else {
        // ---- direct epilogue: sector-efficient scalar stores, no staging ----
#pragma unroll
        for (int ni = 0; ni < 4; ++ni) {
#pragma unroll
            for (int c = 0; c < 2; ++c) {
                int nl = wn + ni * 8 + 2 * tig + c;
                int prow = ODD ? (2 * (rC + nl) + 1)
                               : (jx == 2 ? 4 * nl : 4 * nl + 2);
                float sc = (2.0f / 512.0f) * (prow == 0 ? is2 : 1.0f);
                float* rp = Of + (size_t)prow * DCT_N + yb * BM;
#pragma unroll
                for (int mi = 0; mi < 4; ++mi)
#pragma unroll
                    for (int h = 0; h < 2; ++h) {
                        int ml = wm + mi * 16 + grp + 8 * h;
                        float v = acc[mi][ni][2 * h + c] * sc;
                        if (yb == 0 && ml == 0) v *= is2;
                        __stcs(rp + ml, v);
                    }
            }
        }
    }
}

extern "C" void kernel_launch(void* const* d_in, const int* in_sizes, int n_in,
                              void* d_out, int out_size)
{
    const float* img = (const float*)d_in[0];
    float* out = (float*)d_out;

    static bool attr_set = false;
    if (!attr_set) {
        cudaFuncSetAttribute(dct_fold_fp16<0>,
                             cudaFuncAttributeMaxDynamicSharedMemorySize, SMEM_BYTES);
        cudaFuncSetAttribute(dct_fold_fp16<1>,
                             cudaFuncAttributeMaxDynamicSharedMemorySize, SMEM_BYTES);
        attr_set = true;
    }

    const int tbl_elems = KH * KH + 2 * 128 * 128;   // 98304
    init_tables_kernel<<<(tbl_elems + 255) / 256, 256>>>();

    dim3 grid(4, 4, BATCH);   // jx: {odd0, odd1, ee, eo}
    dct_fold_fp16<0><<<grid, 256, SMEM_BYTES>>>(img, out);
    dct_fold_fp16<1><<<grid, 256, SMEM_BYTES>>>(img, out);
}

// round 14
// speedup vs baseline: 1.0959x; 1.0032x over previous
#include <cuda_runtime.h>
#include <cuda_fp16.h>
#include <cstdint>

// ---------------------------------------------------------------------------
// 2D DCT-II, two-level parity folding, fp16 mma.sync (m16n8k16, fp32 accum).
// R12 base (168.8us): 128x128 CTA tile, 64x32 warp tiles, 2 CTA/SM, BK=64,
// 2-stage buffers, direct pass-B epilogue.
// This round: pass-A ldA (register-path fold loads) moved AFTER compute(t)
// so its LDG->FFMA stall overlaps CP_WAIT0+barrier instead of preceding MMAs.
// Branches per pass (q = transform output index):
//   q odd   : K=256, u1  = x[n]-x[511-n],      tbl cos(pi(2n+1)(2r+1)/1024)
//   q = 4s  : K=128, u00 = lvl2(+) of lvl1(+), tbl cos(pi(2n+1)s/256)
//   q = 4s+2: K=128, u01 = lvl2(-) of lvl1(+), tbl cos(pi(2n+1)(2s+1)/512)
// Pass A CTAs cover i-quads {j0, 511-j0, 255-j0, 256+j0}; epilogue emits
// U1/U00/U01 (both fold levels in fp32) directly. Pass B is pure cp.async.
// ---------------------------------------------------------------------------

#define DCT_N 512
#define BATCH 128
#define KH    256
#define BM    128
#define BN    128
#define BK    64
#define APH   72             // A smem pitch (halfs)
#define BPH   136            // B smem pitch (halfs)
#define SPF   132            // epilogue staging pitch (floats)

#define OFF_A0 0
#define OFF_A1 18432
#define OFF_B0 36864
#define OFF_B1 54272
#define SMEM_BYTES 71680

__device__ __align__(16) __half g_T1 [KH * KH];     // [n][r] cos(pi(2n+1)(2r+1)/1024)
__device__ __align__(16) __half g_TEE[128 * 128];   // [n][s] cos(pi(2n+1)s/256)
__device__ __align__(16) __half g_TEO[128 * 128];   // [n][s] cos(pi(2n+1)(2s+1)/512)
__device__ __align__(16) __half g_U1 [(size_t)BATCH * DCT_N * 256];
__device__ __align__(16) __half g_U00[(size_t)BATCH * DCT_N * 128];
__device__ __align__(16) __half g_U01[(size_t)BATCH * DCT_N * 128];

__global__ void init_tables_kernel() {
    int idx = blockIdx.x * blockDim.x + threadIdx.x;
    if (idx < KH * KH) {
        int n = idx >> 8, r = idx & 255;
        g_T1[idx] = __float2half_rn(
            cospif((2.0f * n + 1.0f) * (2.0f * r + 1.0f) * (1.0f / 1024.0f)));
    } else if (idx < KH * KH + 128 * 128) {
        int j = idx - KH * KH;
        int n = j >> 7, s = j & 127;
        g_TEE[j] = __float2half_rn(
            cospif((2.0f * n + 1.0f) * (float)s * (1.0f / 256.0f)));
    } else if (idx < KH * KH + 2 * 128 * 128) {
        int j = idx - KH * KH - 128 * 128;
        int n = j >> 7, s = j & 127;
        g_TEO[j] = __float2half_rn(
            cospif((2.0f * n + 1.0f) * (2.0f * s + 1.0f) * (1.0f / 512.0f)));
    }
}

__device__ __forceinline__ uint32_t smem_u32(const void* p) {
    uint32_t a;
    asm("{ .reg .u64 t; cvta.to.shared.u64 t, %1; cvt.u32.u64 %0, t; }" : "=r"(a) : "l"(p));
    return a;
}
__device__ __forceinline__ void cp16(uint32_t dst, const void* src) {
    asm volatile("cp.async.cg.shared.global [%0], [%1], 16;" :: "r"(dst), "l"(src));
}
#define CP_COMMIT() asm volatile("cp.async.commit_group;" ::: "memory")
#define CP_WAIT0()  asm volatile("cp.async.wait_group 0;" ::: "memory")

__device__ __forceinline__ void ldsm4(uint32_t r[4], uint32_t addr) {
    asm volatile("ldmatrix.sync.aligned.m8n8.x4.shared.b16 {%0,%1,%2,%3}, [%4];"
                 : "=r"(r[0]), "=r"(r[1]), "=r"(r[2]), "=r"(r[3]) : "r"(addr));
}
__device__ __forceinline__ void ldsm4t(uint32_t r[4], uint32_t addr) {
    asm volatile("ldmatrix.sync.aligned.m8n8.x4.trans.shared.b16 {%0,%1,%2,%3}, [%4];"
                 : "=r"(r[0]), "=r"(r[1]), "=r"(r[2]), "=r"(r[3]) : "r"(addr));
}
__device__ __forceinline__ void mma_f16(float c[4], const uint32_t a[4],
                                        uint32_t b0, uint32_t b1) {
    asm volatile(
        "mma.sync.aligned.m16n8k16.row.col.f32.f16.f16.f32 "
        "{%0,%1,%2,%3},{%4,%5,%6,%7},{%8,%9},{%0,%1,%2,%3};"
        : "+f"(c[0]), "+f"(c[1]), "+f"(c[2]), "+f"(c[3])
        : "r"(a[0]), "r"(a[1]), "r"(a[2]), "r"(a[3]), "r"(b0), "r"(b1));
}
__device__ __forceinline__ uint32_t packh2(float lo, float hi) {
    __half2 h = __floats2half2_rn(lo, hi);
    return *(uint32_t*)&h;
}

// MODE 0: A-source = img (fp32, folded inline), out = U1/U00/U01 (fp16)
// MODE 1: A-source = U1/U00/U01 (pure cp.async), out = d_out (fp32, scaled)
template <int MODE>
__global__ __launch_bounds__(256, 2)
void dct_fold_fp16(const float* __restrict__ img, float* __restrict__ out)
{
    extern __shared__ __align__(16) char smem[];
    const uint32_t sb = smem_u32(smem);
    float* Sf = (float*)smem;

    const int tid = threadIdx.x, lane = tid & 31, warp = tid >> 5;
    const int jx  = blockIdx.x;          // 0,1: odd-q blocks; 2: q=4s; 3: q=4s+2
    const int bat = blockIdx.z;
    const int yb  = blockIdx.y;
    const bool ODD = (jx < 2);
    const int  NT  = ODD ? 4 : 2;        // K / BK
    const int  rC  = ODD ? jx * BN : 0;
    const int  TW  = ODD ? KH : 128;     // table row width
    const __half* tbl = ODD ? g_T1 : (jx == 2 ? g_TEE : g_TEO);
    const float sg2 = (jx == 3) ? -1.0f : 1.0f;
    const int wm = (warp & 1) * 64, wn = (warp >> 1) * 32;
    const int grp = lane >> 2, tig = lane & 3;

    const float* Ef = img + (size_t)bat * DCT_N * DCT_N;
    const __half* Ub =
        ODD ? g_U1 + (size_t)bat * DCT_N * 256
            : (jx == 2 ? g_U00 : g_U01) + (size_t)bat * DCT_N * 128;
    const int UW = ODD ? 256 : 128;
    float* Of = out + (size_t)bat * DCT_N * DCT_N;

    const int aLaneOff =
        ((wm + (lane & 7) + ((lane >> 3) & 1) * 8) * APH + (lane >> 4) * 8) * 2;
    const int bLaneOff =
        (((((lane >> 4) & 1) * 8) + (lane & 7)) * BPH + ((lane >> 3) & 1) * 8) * 2;

    float acc[4][4][4];
#pragma unroll
    for (int mi = 0; mi < 4; ++mi)
#pragma unroll
        for (int ni = 0; ni < 4; ++ni)
#pragma unroll
            for (int r = 0; r < 4; ++r) acc[mi][ni][r] = 0.0f;

    // A-loader coords: 128 rows x 8 granules(8h) -> 4 per thread
    int rowA[4], khh[4];
    const float* rowPtr[4];
#pragma unroll
    for (int i = 0; i < 4; ++i) {
        int g = tid + i * 256;
        rowA[i] = g >> 3;
        khh[i] = (g & 7) * 8;
        if (MODE == 0) {
            int l = rowA[i];
            int j0 = 32 * yb + (l & 31);
            int quad = l >> 5;
            int gi = (quad == 0) ? j0
                   : (quad == 1) ? 511 - j0
                   : (quad == 2) ? 255 - j0
                                 : 256 + j0;
            rowPtr[i] = Ef + (size_t)gi * DCT_N;
        }
    }
    // B-loader coords: 64 rows x 16 granules -> 4 per thread
    int rowB[4], nB[4];
#pragma unroll
    for (int i = 0; i < 4; ++i) {
        int g = tid + i * 256;
        rowB[i] = g >> 4;
        nB[i] = (g & 15) * 8;
    }

    uint4 oReg[4];
    auto ldA = [&](int t) {   // MODE 0 only: fold img -> fp16 regs
#pragma unroll
        for (int i = 0; i < 4; ++i) {
            int kp = t * BK + khh[i];
            const float* base = rowPtr[i];
            float4 F0 = *(const float4*)(base + kp);
            float4 F1 = *(const float4*)(base + kp + 4);
            float4 R1 = *(const float4*)(base + 508 - kp);
            float4 R0 = *(const float4*)(base + 504 - kp);
            if (ODD) {
                oReg[i].x = packh2(F0.x - R1.w, F0.y - R1.z);
                oReg[i].y = packh2(F0.z - R1.y, F0.w - R1.x);
                oReg[i].z = packh2(F1.x - R0.w, F1.y - R0.z);
                oReg[i].w = packh2(F1.z - R0.y, F1.w - R0.x);
            } else {
                float4 C1 = *(const float4*)(base + 252 - kp);
                float4 C0 = *(const float4*)(base + 248 - kp);
                float4 D0 = *(const float4*)(base + 256 + kp);
                float4 D1 = *(const float4*)(base + 260 + kp);
                oReg[i].x = packh2(fmaf(sg2, C1.w + D0.x, F0.x + R1.w),
                                   fmaf(sg2, C1.z + D0.y, F0.y + R1.z));
                oReg[i].y = packh2(fmaf(sg2, C1.y + D0.z, F0.z + R1.y),
                                   fmaf(sg2, C1.x + D0.w, F0.w + R1.x));
                oReg[i].z = packh2(fmaf(sg2, C0.w + D1.x, F1.x + R0.w),
                                   fmaf(sg2, C0.z + D1.y, F1.y + R0.z));
                oReg[i].w = packh2(fmaf(sg2, C0.y + D1.z, F1.z + R0.y),
                                   fmaf(sg2, C0.x + D1.w, F1.w + R0.x));
            }
        }
    };
    auto stsA = [&](int off) {
#pragma unroll
        for (int i = 0; i < 4; ++i)
            *(uint4*)(smem + off + (rowA[i] * APH + khh[i]) * 2) = oReg[i];
    };
    auto cpA = [&](int t, int off) {   // MODE 1: pure async
#pragma unroll
        for (int i = 0; i < 4; ++i) {
            uint32_t dst = sb + off + (rowA[i] * APH + khh[i]) * 2;
            const __half* src = Ub + (size_t)(yb * BM + rowA[i]) * UW + t * BK + khh[i];
            cp16(dst, src);
        }
    };
    auto cpB = [&](int t, int off) {
#pragma unroll
        for (int i = 0; i < 4; ++i) {
            uint32_t dst = sb + off + (rowB[i] * BPH + nB[i]) * 2;
            const __half* src = tbl + (size_t)(t * BK + rowB[i]) * TW + rC + nB[i];
            cp16(dst, src);
        }
    };
    auto compute = [&](int aOff, int bOff) {
#pragma unroll
        for (int ks = 0; ks < 4; ++ks) {
            uint32_t a[4][4];
#pragma unroll
            for (int mi = 0; mi < 4; ++mi)
                ldsm4(a[mi], sb + aOff + aLaneOff + mi * (16 * APH * 2) + ks * 32);
            uint32_t bq[2][4];
#pragma unroll
            for (int pr = 0; pr < 2; ++pr)
                ldsm4t(bq[pr], sb + bOff + bLaneOff + ks * (16 * BPH * 2)
                               + (wn + pr * 16) * 2);
#pragma unroll
            for (int mi = 0; mi < 4; ++mi)
#pragma unroll
                for (int ni = 0; ni < 4; ++ni)
                    mma_f16(acc[mi][ni], a[mi],
                            bq[ni >> 1][ni & 1], bq[ni >> 1][2 + (ni & 1)]);
        }
    };

    const int aOffs[2] = { OFF_A0, OFF_A1 };
    const int bOffs[2] = { OFF_B0, OFF_B1 };

    // ---- prologue ----
    if (MODE == 0) { ldA(0); stsA(aOffs[0]); }
    else           { cpA(0, aOffs[0]); }
    cpB(0, bOffs[0]);
    CP_COMMIT();
    if (MODE == 0) ldA(1);
    CP_WAIT0();
    __syncthreads();

    // ---- mainloop: ldA(t+2) AFTER compute(t) so its LDG->fold stall
    //      overlaps the cp.async drain + barrier instead of preceding MMAs ----
#pragma unroll 1
    for (int t = 0; t < NT; ++t) {
        if (t + 1 < NT) {
            if (MODE == 0) stsA(aOffs[(t + 1) & 1]);
            else           cpA(t + 1, aOffs[(t + 1) & 1]);
            cpB(t + 1, bOffs[(t + 1) & 1]);
            CP_COMMIT();
        }
        compute(aOffs[t & 1], bOffs[t & 1]);
        if (MODE == 0 && t + 2 < NT) ldA(t + 2);
        if (t + 1 < NT) {
            CP_WAIT0();
            __syncthreads();
        }
    }

    const float is2 = 0.70710678118654752440f;
    if (MODE == 0) {
        // ---- staged epilogue (cross-warp folds need smem) ----
        __syncthreads();
#pragma unroll
        for (int mi = 0; mi < 4; ++mi)
#pragma unroll
            for (int ni = 0; ni < 4; ++ni)
#pragma unroll
                for (int h = 0; h < 2; ++h)
#pragma unroll
                    for (int c = 0; c < 2; ++c) {
                        int rl = wn + ni * 8 + 2 * tig + c;
                        int ii = wm + mi * 16 + grp + 8 * h;
                        Sf[rl * SPF + ii] = acc[mi][ni][2 * h + c];
                    }
        __syncthreads();

        __half* U1w  = g_U1  + (size_t)bat * DCT_N * 256;
        __half* U00w = g_U00 + (size_t)bat * DCT_N * 128;
        __half* U01w = g_U01 + (size_t)bat * DCT_N * 128;
#pragma unroll
        for (int it = 0; it < 4; ++it) {
            int idx = it * 256 + tid;
            int rl = idx >> 3;
            int jj4 = (idx & 7) * 4;
            int q = ODD ? (2 * (rC + rl) + 1) : (jx == 2 ? 4 * rl : 4 * rl + 2);
            int j0 = 32 * yb + jj4;
            const float* Sr = Sf + rl * SPF;
            float4 a = *(const float4*)(Sr + jj4);        // T[j0..]
            float4 b = *(const float4*)(Sr + 32 + jj4);   // T[511-j0..]
            float4 c = *(const float4*)(Sr + 64 + jj4);   // T[255-j0..]
            float4 d = *(const float4*)(Sr + 96 + jj4);   // T[256+j0..]
            uint2 u1f, u1r, u00, u01;
            u1f.x = packh2(a.x - b.x, a.y - b.y);
            u1f.y = packh2(a.z - b.z, a.w - b.w);
            u1r.x = packh2(c.w - d.w, c.z - d.z);
            u1r.y = packh2(c.y - d.y, c.x - d.x);
            float e0 = a.x + b.x, e1 = a.y + b.y, e2 = a.z + b.z, e3 = a.w + b.w;
            float f0 = c.x + d.x, f1 = c.y + d.y, f2 = c.z + d.z, f3 = c.w + d.w;
            u00.x = packh2(e0 + f0, e1 + f1);
            u00.y = packh2(e2 + f2, e3 + f3);
            u01.x = packh2(e0 - f0, e1 - f1);
            u01.y = packh2(e2 - f2, e3 - f3);
            *(uint2*)(U1w + (size_t)q * 256 + j0)        = u1f;
            *(uint2*)(U1w + (size_t)q * 256 + 252 - j0)  = u1r;
            *(uint2*)(U00w + (size_t)q * 128 + j0)       = u00;
            *(uint2*)(U01w + (size_t)q * 128 + j0)       = u01;
        }
    } else {
        // ---- direct epilogue: sector-efficient scalar stores, no staging ----
#pragma unroll
        for (int ni = 0; ni < 4; ++ni) {
#pragma unroll
            for (int c = 0; c < 2; ++c) {
                int nl = wn + ni * 8 + 2 * tig + c;
                int prow = ODD ? (2 * (rC + nl) + 1)
                               : (jx == 2 ? 4 * nl : 4 * nl + 2);
                float sc = (2.0f / 512.0f) * (prow == 0 ? is2 : 1.0f);
                float* rp = Of + (size_t)prow * DCT_N + yb * BM;
#pragma unroll
                for (int mi = 0; mi < 4; ++mi)
#pragma unroll
                    for (int h = 0; h < 2; ++h) {
                        int ml = wm + mi * 16 + grp + 8 * h;
                        float v = acc[mi][ni][2 * h + c] * sc;
                        if (yb == 0 && ml == 0) v *= is2;
                        __stcs(rp + ml, v);
                    }
            }
        }
    }
}

extern "C" void kernel_launch(void* const* d_in, const int* in_sizes, int n_in,
                              void* d_out, int out_size)
{
    const float* img = (const float*)d_in[0];
    float* out = (float*)d_out;

    static bool attr_set = false;
    if (!attr_set) {
        cudaFuncSetAttribute(dct_fold_fp16<0>,
                             cudaFuncAttributeMaxDynamicSharedMemorySize, SMEM_BYTES);
        cudaFuncSetAttribute(dct_fold_fp16<1>,
                             cudaFuncAttributeMaxDynamicSharedMemorySize, SMEM_BYTES);
        attr_set = true;
    }

    const int tbl_elems = KH * KH + 2 * 128 * 128;   // 98304
    init_tables_kernel<<<(tbl_elems + 255) / 256, 256>>>();

    dim3 grid(4, 4, BATCH);   // jx: {odd0, odd1, ee, eo}
    dct_fold_fp16<0><<<grid, 256, SMEM_BYTES>>>(img, out);
    dct_fold_fp16<1><<<grid, 256, SMEM_BYTES>>>(img, out);
}

// round 15
// speedup vs baseline: 1.1030x; 1.0065x over previous
#include <cuda_runtime.h>
#include <cuda_fp16.h>
#include <cstdint>

// ---------------------------------------------------------------------------
// 2D DCT-II, two-level parity folding, fp16 mma.sync (m16n8k16, fp32 accum).
// R13 base (168.2us) + Programmatic Dependent Launch at both kernel
// boundaries: passA's img prologue overlaps init_tables; passB's table
// prologue overlaps passA's drain.
// Branches per pass (q = transform output index):
//   q odd   : K=256, u1  = x[n]-x[511-n],      tbl cos(pi(2n+1)(2r+1)/1024)
//   q = 4s  : K=128, u00 = lvl2(+) of lvl1(+), tbl cos(pi(2n+1)s/256)
//   q = 4s+2: K=128, u01 = lvl2(-) of lvl1(+), tbl cos(pi(2n+1)(2s+1)/512)
// ---------------------------------------------------------------------------

#define DCT_N 512
#define BATCH 128
#define KH    256
#define BM    128
#define BN    128
#define BK    64
#define APH   72             // A smem pitch (halfs)
#define BPH   136            // B smem pitch (halfs)
#define SPF   132            // epilogue staging pitch (floats)

#define OFF_A0 0
#define OFF_A1 18432
#define OFF_B0 36864
#define OFF_B1 54272
#define SMEM_BYTES 71680

__device__ __align__(16) __half g_T1 [KH * KH];     // [n][r] cos(pi(2n+1)(2r+1)/1024)
__device__ __align__(16) __half g_TEE[128 * 128];   // [n][s] cos(pi(2n+1)s/256)
__device__ __align__(16) __half g_TEO[128 * 128];   // [n][s] cos(pi(2n+1)(2s+1)/512)
__device__ __align__(16) __half g_U1 [(size_t)BATCH * DCT_N * 256];
__device__ __align__(16) __half g_U00[(size_t)BATCH * DCT_N * 128];
__device__ __align__(16) __half g_U01[(size_t)BATCH * DCT_N * 128];

__global__ void init_tables_kernel() {
    int idx = blockIdx.x * blockDim.x + threadIdx.x;
    if (idx < KH * KH) {
        int n = idx >> 8, r = idx & 255;
        g_T1[idx] = __float2half_rn(
            cospif((2.0f * n + 1.0f) * (2.0f * r + 1.0f) * (1.0f / 1024.0f)));
    } else if (idx < KH * KH + 128 * 128) {
        int j = idx - KH * KH;
        int n = j >> 7, s = j & 127;
        g_TEE[j] = __float2half_rn(
            cospif((2.0f * n + 1.0f) * (float)s * (1.0f / 256.0f)));
    } else if (idx < KH * KH + 2 * 128 * 128) {
        int j = idx - KH * KH - 128 * 128;
        int n = j >> 7, s = j & 127;
        g_TEO[j] = __float2half_rn(
            cospif((2.0f * n + 1.0f) * (2.0f * s + 1.0f) * (1.0f / 512.0f)));
    }
}

__device__ __forceinline__ uint32_t smem_u32(const void* p) {
    uint32_t a;
    asm("{ .reg .u64 t; cvta.to.shared.u64 t, %1; cvt.u32.u64 %0, t; }" : "=r"(a) : "l"(p));
    return a;
}
__device__ __forceinline__ void cp16(uint32_t dst, const void* src) {
    asm volatile("cp.async.cg.shared.global [%0], [%1], 16;" :: "r"(dst), "l"(src));
}
#define CP_COMMIT() asm volatile("cp.async.commit_group;" ::: "memory")
#define CP_WAIT0()  asm volatile("cp.async.wait_group 0;" ::: "memory")

__device__ __forceinline__ void ldsm4(uint32_t r[4], uint32_t addr) {
    asm volatile("ldmatrix.sync.aligned.m8n8.x4.shared.b16 {%0,%1,%2,%3}, [%4];"
                 : "=r"(r[0]), "=r"(r[1]), "=r"(r[2]), "=r"(r[3]) : "r"(addr));
}
__device__ __forceinline__ void ldsm4t(uint32_t r[4], uint32_t addr) {
    asm volatile("ldmatrix.sync.aligned.m8n8.x4.trans.shared.b16 {%0,%1,%2,%3}, [%4];"
                 : "=r"(r[0]), "=r"(r[1]), "=r"(r[2]), "=r"(r[3]) : "r"(addr));
}
__device__ __forceinline__ void mma_f16(float c[4], const uint32_t a[4],
                                        uint32_t b0, uint32_t b1) {
    asm volatile(
        "mma.sync.aligned.m16n8k16.row.col.f32.f16.f16.f32 "
        "{%0,%1,%2,%3},{%4,%5,%6,%7},{%8,%9},{%0,%1,%2,%3};"
        : "+f"(c[0]), "+f"(c[1]), "+f"(c[2]), "+f"(c[3])
        : "r"(a[0]), "r"(a[1]), "r"(a[2]), "r"(a[3]), "r"(b0), "r"(b1));
}
__device__ __forceinline__ uint32_t packh2(float lo, float hi) {
    __half2 h = __floats2half2_rn(lo, hi);
    return *(uint32_t*)&h;
}

// MODE 0: A-source = img (fp32, folded inline), out = U1/U00/U01 (fp16)
// MODE 1: A-source = U1/U00/U01 (pure cp.async), out = d_out (fp32, scaled)
template <int MODE>
__global__ __launch_bounds__(256, 2)
void dct_fold_fp16(const float* __restrict__ img, float* __restrict__ out)
{
    extern __shared__ __align__(16) char smem[];
    const uint32_t sb = smem_u32(smem);
    float* Sf = (float*)smem;

    const int tid = threadIdx.x, lane = tid & 31, warp = tid >> 5;
    const int jx  = blockIdx.x;          // 0,1: odd-q blocks; 2: q=4s; 3: q=4s+2
    const int bat = blockIdx.z;
    const int yb  = blockIdx.y;
    const bool ODD = (jx < 2);
    const int  NT  = ODD ? 4 : 2;        // K / BK
    const int  rC  = ODD ? jx * BN : 0;
    const int  TW  = ODD ? KH : 128;     // table row width
    const __half* tbl = ODD ? g_T1 : (jx == 2 ? g_TEE : g_TEO);
    const float sg2 = (jx == 3) ? -1.0f : 1.0f;
    const int wm = (warp & 1) * 64, wn = (warp >> 1) * 32;
    const int grp = lane >> 2, tig = lane & 3;

    const float* Ef = img + (size_t)bat * DCT_N * DCT_N;
    const __half* Ub =
        ODD ? g_U1 + (size_t)bat * DCT_N * 256
            : (jx == 2 ? g_U00 : g_U01) + (size_t)bat * DCT_N * 128;
    const int UW = ODD ? 256 : 128;
    float* Of = out + (size_t)bat * DCT_N * DCT_N;

    const int aLaneOff =
        ((wm + (lane & 7) + ((lane >> 3) & 1) * 8) * APH + (lane >> 4) * 8) * 2;
    const int bLaneOff =
        (((((lane >> 4) & 1) * 8) + (lane & 7)) * BPH + ((lane >> 3) & 1) * 8) * 2;

    float acc[4][4][4];
#pragma unroll
    for (int mi = 0; mi < 4; ++mi)
#pragma unroll
        for (int ni = 0; ni < 4; ++ni)
#pragma unroll
            for (int r = 0; r < 4; ++r) acc[mi][ni][r] = 0.0f;

    // A-loader coords: 128 rows x 8 granules(8h) -> 4 per thread
    int rowA[4], khh[4];
    const float* rowPtr[4];
#pragma unroll
    for (int i = 0; i < 4; ++i) {
        int g = tid + i * 256;
        rowA[i] = g >> 3;
        khh[i] = (g & 7) * 8;
        if (MODE == 0) {
            int l = rowA[i];
            int j0 = 32 * yb + (l & 31);
            int quad = l >> 5;
            int gi = (quad == 0) ? j0
                   : (quad == 1) ? 511 - j0
                   : (quad == 2) ? 255 - j0
                                 : 256 + j0;
            rowPtr[i] = Ef + (size_t)gi * DCT_N;
        }
    }
    // B-loader coords: 64 rows x 16 granules -> 4 per thread
    int rowB[4], nB[4];
#pragma unroll
    for (int i = 0; i < 4; ++i) {
        int g = tid + i * 256;
        rowB[i] = g >> 4;
        nB[i] = (g & 15) * 8;
    }

    uint4 oReg[4];
    auto ldA = [&](int t) {   // MODE 0 only: fold img -> fp16 regs
#pragma unroll
        for (int i = 0; i < 4; ++i) {
            int kp = t * BK + khh[i];
            const float* base = rowPtr[i];
            float4 F0 = *(const float4*)(base + kp);
            float4 F1 = *(const float4*)(base + kp + 4);
            float4 R1 = *(const float4*)(base + 508 - kp);
            float4 R0 = *(const float4*)(base + 504 - kp);
            if (ODD) {
                oReg[i].x = packh2(F0.x - R1.w, F0.y - R1.z);
                oReg[i].y = packh2(F0.z - R1.y, F0.w - R1.x);
                oReg[i].z = packh2(F1.x - R0.w, F1.y - R0.z);
                oReg[i].w = packh2(F1.z - R0.y, F1.w - R0.x);
            } else {
                float4 C1 = *(const float4*)(base + 252 - kp);
                float4 C0 = *(const float4*)(base + 248 - kp);
                float4 D0 = *(const float4*)(base + 256 + kp);
                float4 D1 = *(const float4*)(base + 260 + kp);
                oReg[i].x = packh2(fmaf(sg2, C1.w + D0.x, F0.x + R1.w),
                                   fmaf(sg2, C1.z + D0.y, F0.y + R1.z));
                oReg[i].y = packh2(fmaf(sg2, C1.y + D0.z, F0.z + R1.y),
                                   fmaf(sg2, C1.x + D0.w, F0.w + R1.x));
                oReg[i].z = packh2(fmaf(sg2, C0.w + D1.x, F1.x + R0.w),
                                   fmaf(sg2, C0.z + D1.y, F1.y + R0.z));
                oReg[i].w = packh2(fmaf(sg2, C0.y + D1.z, F1.z + R0.y),
                                   fmaf(sg2, C0.x + D1.w, F1.w + R0.x));
            }
        }
    };
    auto stsA = [&](int off) {
#pragma unroll
        for (int i = 0; i < 4; ++i)
            *(uint4*)(smem + off + (rowA[i] * APH + khh[i]) * 2) = oReg[i];
    };
    auto cpA = [&](int t, int off) {   // MODE 1: pure async
#pragma unroll
        for (int i = 0; i < 4; ++i) {
            uint32_t dst = sb + off + (rowA[i] * APH + khh[i]) * 2;
            const __half* src = Ub + (size_t)(yb * BM + rowA[i]) * UW + t * BK + khh[i];
            cp16(dst, src);
        }
    };
    auto cpB = [&](int t, int off) {
#pragma unroll
        for (int i = 0; i < 4; ++i) {
            uint32_t dst = sb + off + (rowB[i] * BPH + nB[i]) * 2;
            const __half* src = tbl + (size_t)(t * BK + rowB[i]) * TW + rC + nB[i];
            cp16(dst, src);
        }
    };
    auto compute = [&](int aOff, int bOff) {
#pragma unroll
        for (int ks = 0; ks < 4; ++ks) {
            uint32_t a[4][4];
#pragma unroll
            for (int mi = 0; mi < 4; ++mi)
                ldsm4(a[mi], sb + aOff + aLaneOff + mi * (16 * APH * 2) + ks * 32);
            uint32_t bq[2][4];
#pragma unroll
            for (int pr = 0; pr < 2; ++pr)
                ldsm4t(bq[pr], sb + bOff + bLaneOff + ks * (16 * BPH * 2)
                               + (wn + pr * 16) * 2);
#pragma unroll
            for (int mi = 0; mi < 4; ++mi)
#pragma unroll
                for (int ni = 0; ni < 4; ++ni)
                    mma_f16(acc[mi][ni], a[mi],
                            bq[ni >> 1][ni & 1], bq[ni >> 1][2 + (ni & 1)]);
        }
    };

    const int aOffs[2] = { OFF_A0, OFF_A1 };
    const int bOffs[2] = { OFF_B0, OFF_B1 };

    // ---- prologue (PDL-split) ----
    if (MODE == 0) {
        // pre-sync: img only (init_tables never touches img)
        ldA(0); stsA(aOffs[0]);
        cudaGridDependencySynchronize();      // wait: cos tables ready
        cpB(0, bOffs[0]);
        CP_COMMIT();
        ldA(1);
    } else {
        // pre-sync: cos tables only (written by init, independent of pass A)
        cpB(0, bOffs[0]);
        cudaGridDependencySynchronize();      // wait: U1/U00/U01 ready
        cpA(0, aOffs[0]);
        CP_COMMIT();
    }
    CP_WAIT0();
    __syncthreads();

    // ---- mainloop (R13 schedule, untouched) ----
#pragma unroll 1
    for (int t = 0; t < NT; ++t) {
        if (t + 1 < NT) {
            if (MODE == 0) stsA(aOffs[(t + 1) & 1]);
            else           cpA(t + 1, aOffs[(t + 1) & 1]);
            cpB(t + 1, bOffs[(t + 1) & 1]);
            CP_COMMIT();
        }
        compute(aOffs[t & 1], bOffs[t & 1]);
        if (MODE == 0 && t + 2 < NT) ldA(t + 2);
        if (t + 1 < NT) {
            CP_WAIT0();
            __syncthreads();
        }
    }

    const float is2 = 0.70710678118654752440f;
    if (MODE == 0) {
        // ---- staged epilogue (cross-warp folds need smem) ----
        __syncthreads();
#pragma unroll
        for (int mi = 0; mi < 4; ++mi)
#pragma unroll
            for (int ni = 0; ni < 4; ++ni)
#pragma unroll
                for (int h = 0; h < 2; ++h)
#pragma unroll
                    for (int c = 0; c < 2; ++c) {
                        int rl = wn + ni * 8 + 2 * tig + c;
                        int ii = wm + mi * 16 + grp + 8 * h;
                        Sf[rl * SPF + ii] = acc[mi][ni][2 * h + c];
                    }
        __syncthreads();

        __half* U1w  = g_U1  + (size_t)bat * DCT_N * 256;
        __half* U00w = g_U00 + (size_t)bat * DCT_N * 128;
        __half* U01w = g_U01 + (size_t)bat * DCT_N * 128;
#pragma unroll
        for (int it = 0; it < 4; ++it) {
            int idx = it * 256 + tid;
            int rl = idx >> 3;
            int jj4 = (idx & 7) * 4;
            int q = ODD ? (2 * (rC + rl) + 1) : (jx == 2 ? 4 * rl : 4 * rl + 2);
            int j0 = 32 * yb + jj4;
            const float* Sr = Sf + rl * SPF;
            float4 a = *(const float4*)(Sr + jj4);        // T[j0..]
            float4 b = *(const float4*)(Sr + 32 + jj4);   // T[511-j0..]
            float4 c = *(const float4*)(Sr + 64 + jj4);   // T[255-j0..]
            float4 d = *(const float4*)(Sr + 96 + jj4);   // T[256+j0..]
            uint2 u1f, u1r, u00, u01;
            u1f.x = packh2(a.x - b.x, a.y - b.y);
            u1f.y = packh2(a.z - b.z, a.w - b.w);
            u1r.x = packh2(c.w - d.w, c.z - d.z);
            u1r.y = packh2(c.y - d.y, c.x - d.x);
            float e0 = a.x + b.x, e1 = a.y + b.y, e2 = a.z + b.z, e3 = a.w + b.w;
            float f0 = c.x + d.x, f1 = c.y + d.y, f2 = c.z + d.z, f3 = c.w + d.w;
            u00.x = packh2(e0 + f0, e1 + f1);
            u00.y = packh2(e2 + f2, e3 + f3);
            u01.x = packh2(e0 - f0, e1 - f1);
            u01.y = packh2(e2 - f2, e3 - f3);
            *(uint2*)(U1w + (size_t)q * 256 + j0)        = u1f;
            *(uint2*)(U1w + (size_t)q * 256 + 252 - j0)  = u1r;
            *(uint2*)(U00w + (size_t)q * 128 + j0)       = u00;
            *(uint2*)(U01w + (size_t)q * 128 + j0)       = u01;
        }
        // allow pass B to launch while our stores drain
        cudaTriggerProgrammaticLaunchCompletion();
    } else {
        // ---- direct epilogue: sector-efficient scalar stores, no staging ----
#pragma unroll
        for (int ni = 0; ni < 4; ++ni) {
#pragma unroll
            for (int c = 0; c < 2; ++c) {
                int nl = wn + ni * 8 + 2 * tig + c;
                int prow = ODD ? (2 * (rC + nl) + 1)
                               : (jx == 2 ? 4 * nl : 4 * nl + 2);
                float sc = (2.0f / 512.0f) * (prow == 0 ? is2 : 1.0f);
                float* rp = Of + (size_t)prow * DCT_N + yb * BM;
#pragma unroll
                for (int mi = 0; mi < 4; ++mi)
#pragma unroll
                    for (int h = 0; h < 2; ++h) {
                        int ml = wm + mi * 16 + grp + 8 * h;
                        float v = acc[mi][ni][2 * h + c] * sc;
                        if (yb == 0 && ml == 0) v *= is2;
                        __stcs(rp + ml, v);
                    }
            }
        }
    }
}

extern "C" void kernel_launch(void* const* d_in, const int* in_sizes, int n_in,
                              void* d_out, int out_size)
{
    const float* img = (const float*)d_in[0];
    float* out = (float*)d_out;

    static bool attr_set = false;
    if (!attr_set) {
        cudaFuncSetAttribute(dct_fold_fp16<0>,
                             cudaFuncAttributeMaxDynamicSharedMemorySize, SMEM_BYTES);
        cudaFuncSetAttribute(dct_fold_fp16<1>,
                             cudaFuncAttributeMaxDynamicSharedMemorySize, SMEM_BYTES);
        attr_set = true;
    }

    const int tbl_elems = KH * KH + 2 * 128 * 128;   // 98304
    init_tables_kernel<<<(tbl_elems + 255) / 256, 256>>>();

    dim3 grid(4, 4, BATCH);   // jx: {odd0, odd1, ee, eo}

    cudaLaunchAttribute attrs[1];
    attrs[0].id = cudaLaunchAttributeProgrammaticStreamSerialization;
    attrs[0].val.programmaticStreamSerializationAllowed = 1;

    cudaLaunchConfig_t cfg = {};
    cfg.gridDim = grid;
    cfg.blockDim = dim3(256, 1, 1);
    cfg.dynamicSmemBytes = SMEM_BYTES;
    cfg.stream = 0;
    cfg.attrs = attrs;
    cfg.numAttrs = 1;

    cudaLaunchKernelEx(&cfg, dct_fold_fp16<0>, img, out);
    cudaLaunchKernelEx(&cfg, dct_fold_fp16<1>, img, out);
}